// round 7
// baseline (speedup 1.0000x reference)
#include <cuda_runtime.h>
#include <math.h>

#define B 128

__device__ float g_h1[B * 1024];
__device__ float g_h2[B * 512];
__device__ float g_h3[B * 256];

__device__ __forceinline__ float ex2f(float x) {
    float y;
    asm("ex2.approx.f32 %0, %1;" : "=f"(y) : "f"(x));
    return y;
}

// packed fp32 pair ops (FFMA2 pipe — PTX-only encodings on sm_103a)
__device__ __forceinline__ unsigned long long mul2(unsigned long long a, unsigned long long b) {
    unsigned long long r;
    asm("mul.rn.f32x2 %0, %1, %2;" : "=l"(r) : "l"(a), "l"(b));
    return r;
}
__device__ __forceinline__ unsigned long long add2(unsigned long long a, unsigned long long b) {
    unsigned long long r;
    asm("add.rn.f32x2 %0, %1, %2;" : "=l"(r) : "l"(a), "l"(b));
    return r;
}
__device__ __forceinline__ unsigned long long fma2(unsigned long long a, unsigned long long b,
                                                   unsigned long long c) {
    unsigned long long r;
    asm("fma.rn.f32x2 %0, %1, %2, %3;" : "=l"(r) : "l"(a), "l"(b), "l"(c));
    return r;
}
__device__ __forceinline__ unsigned long long pack2(float lo, float hi) {
    unsigned long long r;
    asm("mov.b64 %0, {%1, %2};" : "=l"(r) : "f"(lo), "f"(hi));
    return r;
}
__device__ __forceinline__ void unpack2(unsigned long long v, float& lo, float& hi) {
    asm("mov.b64 {%0, %1}, %2;" : "=f"(lo), "=f"(hi) : "l"(v));
}
// 2^z for both halves of a packed pair
__device__ __forceinline__ unsigned long long ex2pair(unsigned long long z) {
    float z0, z1;
    unpack2(z, z0, z1);
    return pack2(ex2f(z0), ex2f(z1));
}

// identity on [0,1], slope 0.1 outside — branch-free:
// r = min(max(x, 0.1x), 0.1x + 0.9)
__device__ __forceinline__ float leaky_clamp01(float w) {
    return fminf(fmaxf(w, 0.1f * w), fmaf(0.1f, w, 0.9f));
}

__device__ __forceinline__ float tau_scale(const float* taup, float tau_floor) {
    float ta  = __ldg(taup);
    float tau = tau_floor + (ta >= 0.0f ? ta : 0.05f * ta);  // leaky_relu
    return tau * 1.4426950408889634f;                        // tau * log2(e)
}

// ============================================================================
// Unified layer kernel.
//   out[b,o] = 1 - (sum_i e^arg * arg)/(cs * sum_i e^arg), arg = cs*h[b,i]*aw[o,i]
// Tile: BT batch rows x OT outputs, K staged in KC chunks.
// S-way K split: thread (idx, s) covers [s*KC/S, (s+1)*KC/S) of each chunk;
// num/den partials are additive, reduced through smem.
// Inner loop uses packed f32x2 mul/add/fma; only ex2 is scalar.
// CAT: layer-0 mode, h is x[B][IN/2], staged on the fly as concat(x, 1-x).
// ============================================================================
template <int IN, int BT, int OT, int KC, int S, bool CAT>
__global__ __launch_bounds__(BT * OT * S) void layer_kernel(
    const float* __restrict__ h, const float* __restrict__ W,
    const float* __restrict__ taup, float tau_floor,
    float* __restrict__ out, int out_dim) {
    constexpr int G   = BT * OT;      // outputs per block
    constexpr int T   = G * S;        // threads per block
    constexpr int KR  = KC / S;       // K range per thread per chunk
    constexpr int KCP = KC + 4;       // row pad: 16B-aligned rows, bank spread
    __shared__ float  ch[BT * KCP];
    __shared__ float  aw[OT * KCP];
    __shared__ float2 rpart[S > 1 ? T : 1];   // (num, den) partials

    const int tid   = threadIdx.x;
    const int obase = blockIdx.x * OT;
    const int bbase = blockIdx.y * BT;
    const int idx   = tid % G;
    const int s     = tid / G;
    const int b     = idx % BT;
    const int o     = idx / BT;

    const float cs = tau_scale(taup, tau_floor);

    unsigned long long numP = 0ull, denP = 0ull;   // packed (lo,hi) accumulators

    for (int k0 = 0; k0 < IN; k0 += KC) {
        if (k0) __syncthreads();
        {   // stage activations (fused concat(x,1-x) for layer 0)
            const bool inv  = CAT && (k0 >= IN / 2);
            const float sc  = inv ? -cs : cs;
            const float off = inv ?  cs : 0.0f;
            const int hk0   = CAT ? (k0 & (IN / 2 - 1)) : k0;
            const int hstr  = CAT ? (IN / 2) : IN;
            #pragma unroll
            for (int i = tid; i < BT * (KC / 4); i += T) {
                int bb = i / (KC / 4), kv = i - bb * (KC / 4);
                float4 v = *(const float4*)&h[(bbase + bb) * hstr + hk0 + kv * 4];
                float4 r;
                r.x = fmaf(v.x, sc, off); r.y = fmaf(v.y, sc, off);
                r.z = fmaf(v.z, sc, off); r.w = fmaf(v.w, sc, off);
                *(float4*)&ch[bb * KCP + kv * 4] = r;
            }
        }
        #pragma unroll
        for (int i = tid; i < OT * (KC / 4); i += T) {
            int oo = i / (KC / 4), kv = i - oo * (KC / 4);
            float4 v = *(const float4*)&W[(obase + oo) * IN + k0 + kv * 4];
            float4 r;
            r.x = leaky_clamp01(v.x); r.y = leaky_clamp01(v.y);
            r.z = leaky_clamp01(v.z); r.w = leaky_clamp01(v.w);
            *(float4*)&aw[oo * KCP + kv * 4] = r;
        }
        __syncthreads();

        const float* cp = &ch[b * KCP + s * KR];
        const float* ap = &aw[o * KCP + s * KR];
        #pragma unroll 4
        for (int k = 0; k < KR; k += 4) {
            ulonglong2 c = *(const ulonglong2*)&cp[k];   // 2 packed pairs
            ulonglong2 a = *(const ulonglong2*)&ap[k];
            unsigned long long z01 = mul2(c.x, a.x);
            unsigned long long z23 = mul2(c.y, a.y);
            unsigned long long e01 = ex2pair(z01);
            unsigned long long e23 = ex2pair(z23);
            denP = add2(denP, e01);
            numP = fma2(e01, z01, numP);
            denP = add2(denP, e23);
            numP = fma2(e23, z23, numP);
        }
    }

    float n0, n1, d0, d1;
    unpack2(numP, n0, n1);
    unpack2(denP, d0, d1);
    float num = n0 + n1, den = d0 + d1;

    if (S > 1) {
        rpart[tid] = make_float2(num, den);
        __syncthreads();
        if (s == 0) {
            #pragma unroll
            for (int ss = 1; ss < S; ss++) {
                float2 p = rpart[idx + ss * G];
                num += p.x;
                den += p.y;
            }
            out[(bbase + b) * out_dim + obase + o] = 1.0f - (num / den) / cs;
        }
    } else {
        out[(bbase + b) * out_dim + obase + o] = 1.0f - (num / den) / cs;
    }
}

extern "C" void kernel_launch(void* const* d_in, const int* in_sizes, int n_in,
                              void* d_out, int out_size) {
    // metadata order: x, W0, tau0, W1, tau1, W2, tau2, W3, tau3
    const float* x  = (const float*)d_in[0];
    const float* W0 = (const float*)d_in[1];
    const float* t0 = (const float*)d_in[2];
    const float* W1 = (const float*)d_in[3];
    const float* t1 = (const float*)d_in[4];
    const float* W2 = (const float*)d_in[5];
    const float* t2 = (const float*)d_in[6];
    const float* W3 = (const float*)d_in[7];
    const float* t3 = (const float*)d_in[8];
    float* out = (float*)d_out;

    float *h1, *h2, *h3;
    cudaGetSymbolAddress((void**)&h1, g_h1);
    cudaGetSymbolAddress((void**)&h2, g_h2);
    cudaGetSymbolAddress((void**)&h3, g_h3);

    // tau_floor = log(in-1) + log(0.95/0.05)
    const float L19 = 2.9444389791664403f;
    const float tf0 = logf(1023.0f) + L19;
    const float tf1 = logf(1023.0f) + L19;
    const float tf2 = logf(511.0f)  + L19;
    const float tf3 = logf(255.0f)  + L19;

    // L0: 1024->1024, fused concat. 512 blocks x 512 thr = 8192 warps.
    layer_kernel<1024, 16, 16, 256, 2, true>
        <<<dim3(1024 / 16, B / 16), 16 * 16 * 2>>>(x, W0, t0, tf0, h1, 1024);
    // L1: 1024->512. 512 blocks x 256 thr = 4096 warps.
    layer_kernel<1024, 8, 16, 256, 2, false>
        <<<dim3(512 / 16, B / 8), 8 * 16 * 2>>>(h1, W1, t1, tf1, h2, 512);
    // L2: 512->256, single chunk, 4-way split. 512 blocks x 256 thr.
    layer_kernel<512, 8, 8, 512, 4, false>
        <<<dim3(256 / 8, B / 8), 8 * 8 * 4>>>(h2, W2, t2, tf2, h3, 256);
    // L3: 256->128, single chunk, 4-way split (R5-proven shape). 256 blocks x 256 thr.
    layer_kernel<256, 8, 8, 256, 4, false>
        <<<dim3(128 / 8, B / 8), 8 * 8 * 4>>>(h3, W3, t3, tf3, out, 128);
}

// round 8
// speedup vs baseline: 1.5287x; 1.5287x over previous
#include <cuda_runtime.h>
#include <math.h>

#define B 128

__device__ float g_h1[B * 1024];
__device__ float g_h2[B * 512];
__device__ float g_h3[B * 256];

__device__ __forceinline__ float ex2f(float x) {
    float y;
    asm("ex2.approx.f32 %0, %1;" : "=f"(y) : "f"(x));
    return y;
}

// identity on [0,1], slope 0.1 outside
__device__ __forceinline__ float leaky_clamp01(float w) {
    float r = w;
    if (w < 0.0f)      r = 0.1f * w;
    else if (w > 1.0f) r = 1.0f + 0.1f * (w - 1.0f);
    return r;
}

__device__ __forceinline__ float tau_scale(const float* taup, float tau_floor) {
    float ta  = __ldg(taup);
    float tau = tau_floor + (ta >= 0.0f ? ta : 0.05f * ta);  // leaky_relu
    return tau * 1.4426950408889634f;                        // tau * log2(e)
}

// ============================================================================
// Chunked kernel (big layers). Thread owns 2 outputs (oh, oh+OT/2) for one
// batch row, covering K range [s*KC/S, (s+1)*KC/S) of each staged chunk.
// S-way partials (num, den additive) reduced via smem at the end.
//   out[b,o] = 1 - (sum e^arg * arg)/(cs * sum e^arg), arg = cs*h[b,i]*aw[o,i]
// CAT: layer-0 mode, h is x[B][IN/2], staged as concat(x, 1-x).
// ============================================================================
template <int IN, int BT, int OT, int KC, int S, bool CAT>
__global__ __launch_bounds__(BT*(OT/2)*S) void layer_chunked(
    const float* __restrict__ h, const float* __restrict__ W,
    const float* __restrict__ taup, float tau_floor,
    float* __restrict__ out, int out_dim) {
    constexpr int G   = BT * (OT / 2);   // thread groups (2 outputs each)
    constexpr int T   = G * S;
    constexpr int OH  = OT / 2;
    constexpr int KR  = KC / S;
    constexpr int KCP = KC + 4;
    __shared__ float  ch[BT * KCP];
    __shared__ float  aw[OT * KCP];
    __shared__ float4 rpart[S > 1 ? T : 1];  // (num0, den0, num1, den1)

    const int tid   = threadIdx.x;
    const int obase = blockIdx.x * OT;
    const int bbase = blockIdx.y * BT;
    const int idx   = tid % G;
    const int s     = tid / G;
    const int b     = idx % BT;
    const int oh    = idx / BT;

    const float cs = tau_scale(taup, tau_floor);

    float num0 = 0.f, den0 = 0.f, num1 = 0.f, den1 = 0.f;

    for (int k0 = 0; k0 < IN; k0 += KC) {
        if (k0) __syncthreads();
        {   // stage activations (fused concat(x,1-x) for layer 0)
            const bool inv  = CAT && (k0 >= IN / 2);
            const float sc  = inv ? -cs : cs;
            const float off = inv ?  cs : 0.0f;
            const int hk0   = CAT ? (k0 & (IN / 2 - 1)) : k0;
            const int hstr  = CAT ? (IN / 2) : IN;
            #pragma unroll
            for (int i = tid; i < BT * (KC / 4); i += T) {
                int bb = i / (KC / 4), kv = i - bb * (KC / 4);
                float4 v = *(const float4*)&h[(bbase + bb) * hstr + hk0 + kv * 4];
                float4 r;
                r.x = fmaf(v.x, sc, off); r.y = fmaf(v.y, sc, off);
                r.z = fmaf(v.z, sc, off); r.w = fmaf(v.w, sc, off);
                *(float4*)&ch[bb * KCP + kv * 4] = r;
            }
        }
        #pragma unroll
        for (int i = tid; i < OT * (KC / 4); i += T) {
            int oo = i / (KC / 4), kv = i - oo * (KC / 4);
            float4 v = *(const float4*)&W[(obase + oo) * IN + k0 + kv * 4];
            float4 r;
            r.x = leaky_clamp01(v.x); r.y = leaky_clamp01(v.y);
            r.z = leaky_clamp01(v.z); r.w = leaky_clamp01(v.w);
            *(float4*)&aw[oo * KCP + kv * 4] = r;
        }
        __syncthreads();

        const float* cp  = &ch[b * KCP + s * KR];
        const float* ap0 = &aw[oh * KCP + s * KR];
        const float* ap1 = &aw[(oh + OH) * KCP + s * KR];
        #pragma unroll 4
        for (int k = 0; k < KR; k += 4) {
            float4 c  = *(const float4*)&cp[k];
            float4 a0 = *(const float4*)&ap0[k];
            float4 a1 = *(const float4*)&ap1[k];
            float z;
            z = c.x * a0.x; { float e = ex2f(z); den0 += e; num0 = fmaf(e, z, num0); }
            z = c.y * a0.y; { float e = ex2f(z); den0 += e; num0 = fmaf(e, z, num0); }
            z = c.z * a0.z; { float e = ex2f(z); den0 += e; num0 = fmaf(e, z, num0); }
            z = c.w * a0.w; { float e = ex2f(z); den0 += e; num0 = fmaf(e, z, num0); }
            z = c.x * a1.x; { float e = ex2f(z); den1 += e; num1 = fmaf(e, z, num1); }
            z = c.y * a1.y; { float e = ex2f(z); den1 += e; num1 = fmaf(e, z, num1); }
            z = c.z * a1.z; { float e = ex2f(z); den1 += e; num1 = fmaf(e, z, num1); }
            z = c.w * a1.w; { float e = ex2f(z); den1 += e; num1 = fmaf(e, z, num1); }
        }
    }

    if (S > 1) {
        rpart[tid] = make_float4(num0, den0, num1, den1);
        __syncthreads();
        if (s == 0) {
            #pragma unroll
            for (int ss = 1; ss < S; ss++) {
                float4 p = rpart[idx + ss * G];
                num0 += p.x; den0 += p.y; num1 += p.z; den1 += p.w;
            }
            const int bo = (bbase + b) * out_dim + obase + oh;
            out[bo]      = 1.0f - (num0 / den0) / cs;
            out[bo + OH] = 1.0f - (num1 / den1) / cs;
        }
    } else {
        const int bo = (bbase + b) * out_dim + obase + oh;
        out[bo]      = 1.0f - (num0 / den0) / cs;
        out[bo + OH] = 1.0f - (num1 / den1) / cs;
    }
}

// ============================================================================
// Split kernel (small layers). Whole input staged once; S threads per output,
// each covering IN/S of K; partials reduced via smem. (R5-proven.)
// ============================================================================
template <int IN, int BT, int OT, int S>
__global__ __launch_bounds__(BT * OT * S) void layer_split(
    const float* __restrict__ h, const float* __restrict__ W,
    const float* __restrict__ taup, float tau_floor,
    float* __restrict__ out, int out_dim) {
    constexpr int T   = BT * OT * S;
    constexpr int G   = BT * OT;
    constexpr int KR  = IN / S;
    constexpr int INP = IN + 4;
    __shared__ float ch[BT * INP];
    __shared__ float aw[OT * INP];
    __shared__ float2 rpart[T];

    const int tid   = threadIdx.x;
    const int obase = blockIdx.x * OT;
    const int bbase = blockIdx.y * BT;
    const int idx   = tid & (G - 1);
    const int s     = tid / G;
    const int b     = idx % BT;
    const int o     = idx / BT;

    const float cs = tau_scale(taup, tau_floor);

    #pragma unroll
    for (int i = tid; i < BT * (IN / 4); i += T) {
        int bb = i / (IN / 4), kv = i - bb * (IN / 4);
        float4 v = *(const float4*)&h[(bbase + bb) * IN + kv * 4];
        float4 r; r.x = v.x * cs; r.y = v.y * cs; r.z = v.z * cs; r.w = v.w * cs;
        *(float4*)&ch[bb * INP + kv * 4] = r;
    }
    #pragma unroll
    for (int i = tid; i < OT * (IN / 4); i += T) {
        int oo = i / (IN / 4), kv = i - oo * (IN / 4);
        float4 v = *(const float4*)&W[(obase + oo) * IN + kv * 4];
        float4 r;
        r.x = leaky_clamp01(v.x); r.y = leaky_clamp01(v.y);
        r.z = leaky_clamp01(v.z); r.w = leaky_clamp01(v.w);
        *(float4*)&aw[oo * INP + kv * 4] = r;
    }
    __syncthreads();

    float num = 0.0f, den = 0.0f;
    const float* cp = &ch[b * INP + s * KR];
    const float* ap = &aw[o * INP + s * KR];
    #pragma unroll 4
    for (int k = 0; k < KR; k += 4) {
        float4 c = *(const float4*)&cp[k];
        float4 a = *(const float4*)&ap[k];
        float z;
        z = c.x * a.x; { float e = ex2f(z); den += e; num = fmaf(e, z, num); }
        z = c.y * a.y; { float e = ex2f(z); den += e; num = fmaf(e, z, num); }
        z = c.z * a.z; { float e = ex2f(z); den += e; num = fmaf(e, z, num); }
        z = c.w * a.w; { float e = ex2f(z); den += e; num = fmaf(e, z, num); }
    }

    rpart[tid] = make_float2(num, den);
    __syncthreads();
    if (s == 0) {
        #pragma unroll
        for (int ss = 1; ss < S; ss++) {
            float2 p = rpart[idx + ss * G];
            num += p.x;
            den += p.y;
        }
        out[(bbase + b) * out_dim + obase + o] = 1.0f - (num / den) / cs;
    }
}

extern "C" void kernel_launch(void* const* d_in, const int* in_sizes, int n_in,
                              void* d_out, int out_size) {
    // metadata order: x, W0, tau0, W1, tau1, W2, tau2, W3, tau3
    const float* x  = (const float*)d_in[0];
    const float* W0 = (const float*)d_in[1];
    const float* t0 = (const float*)d_in[2];
    const float* W1 = (const float*)d_in[3];
    const float* t1 = (const float*)d_in[4];
    const float* W2 = (const float*)d_in[5];
    const float* t2 = (const float*)d_in[6];
    const float* W3 = (const float*)d_in[7];
    const float* t3 = (const float*)d_in[8];
    float* out = (float*)d_out;

    float *h1, *h2, *h3;
    cudaGetSymbolAddress((void**)&h1, g_h1);
    cudaGetSymbolAddress((void**)&h2, g_h2);
    cudaGetSymbolAddress((void**)&h3, g_h3);

    // tau_floor = log(in-1) + log(0.95/0.05)
    const float L19 = 2.9444389791664403f;
    const float tf0 = logf(1023.0f) + L19;
    const float tf1 = logf(1023.0f) + L19;
    const float tf2 = logf(511.0f)  + L19;
    const float tf3 = logf(255.0f)  + L19;

    // L0: 1024->1024, fused concat, S=2. 512 blocks x 256 thr = 4096 warps.
    layer_chunked<1024, 8, 32, 256, 2, true>
        <<<dim3(1024 / 32, B / 8), 256>>>(x, W0, t0, tf0, h1, 1024);
    // L1: 1024->512, S=4. 256 blocks x 512 thr = 4096 warps.
    layer_chunked<1024, 8, 32, 256, 4, false>
        <<<dim3(512 / 32, B / 8), 512>>>(h1, W1, t1, tf1, h2, 512);
    // L2: 512->256, 4-way split. 512 blocks x 256 thr.
    layer_split<512, 8, 8, 4>
        <<<dim3(256 / 8, B / 8), 256>>>(h2, W2, t2, tf2, h3, 256);
    // L3: 256->128, 4-way split. 256 blocks x 256 thr.
    layer_split<256, 8, 8, 4>
        <<<dim3(128 / 8, B / 8), 256>>>(h3, W3, t3, tf3, out, 128);
}